// round 9
// baseline (speedup 1.0000x reference)
#include <cuda_runtime.h>
#include <math.h>

#define BB 4
#define CC 3
#define HH 384
#define WW 384
#define HWSZ (HH * WW)
#define CHW (CC * HWSZ)

#define INV2SC 50.0f            // 1/(2*0.1^2)
#define INV2SS (1.0f / 98.0f)   // 1/(2*7^2)
#define EPS_LP 1e-6f

// Border pixels per image: 2 strips of 3x384 + 378 rows x 6 cols
#define NBORDER (2 * 3 * WW + (HH - 6) * 6)   // 4572
#define NBTOT (NBORDER * BB)                  // 18288

// lp(d) = (d*d + eps)^0.4
__device__ __forceinline__ float lp_term(float d) {
    return __powf(fmaf(d, d, EPS_LP), 0.4f);
}

// One ordered pair term: wcs*sm + (ws-wcs)*ed
__device__ __forceinline__ float pair_term(
    float i0, float i1, float i2, float t0, float t1, float t2,
    float iq0, float iq1, float iq2, float tq0, float tq1, float tq2,
    float ws, float sconst)
{
    const float d0 = i0 - iq0, d1 = i1 - iq1, d2 = i2 - iq2;
    const float e0 = t0 - tq0, e1 = t1 - tq1, e2 = t2 - tq2;
    const float cd = fmaf(e0, e0, fmaf(e1, e1, e2 * e2));
    const float wcs = __expf(-fmaf(cd, INV2SC, sconst));   // ws*wc fused
    const float sm = lp_term(d0) + lp_term(d1) + lp_term(d2);
    const float ed = lp_term(fabsf(d0) - fabsf(e0))
                   + lp_term(fabsf(d1) - fabsf(e1))
                   + lp_term(fabsf(d2) - fabsf(e2));
    return fmaf(wcs, sm, (ws - wcs) * ed);
}

// warp -> block reduction, one atomic per block (pre-scaled by 1/n)
__device__ __forceinline__ void reduce_add(float acc, float* out, int tid) {
    const unsigned FULL = 0xFFFFFFFFu;
#pragma unroll
    for (int off = 16; off > 0; off >>= 1)
        acc += __shfl_down_sync(FULL, acc, off);
    __shared__ float wsum[8];
    const int wid = tid >> 5, lid = tid & 31;
    if (lid == 0) wsum[wid] = acc;
    __syncthreads();
    if (wid == 0) {
        float v = (lid < 8) ? wsum[lid] : 0.0f;
#pragma unroll
        for (int off = 4; off > 0; off >>= 1)
            v += __shfl_down_sync(FULL, v, off);
        if (lid == 0) {
            const float inv_n = 1.0f / (float)(BB * CC * HH * WW);
            atomicAdd(out, v * inv_n);
        }
    }
}

// Main kernel: each thread owns TWO x-adjacent pixels (x0 even, x1 = x0+1).
// Half-set (dy>0, or dy==0 && dx>0), in-bounds neighbors, terms counted twice.
// Load reuse: pixel0 @ dx=k and pixel1 @ dx=k-1 read the SAME column x0+k.
__global__ __launch_bounds__(256)
void pair_kernel(const float* __restrict__ inp,
                 const float* __restrict__ tgt,
                 float* __restrict__ out) {
    const int x0 = (blockIdx.x * 32 + threadIdx.x) * 2;
    const int y  = blockIdx.y * 8 + threadIdx.y;
    const int b  = blockIdx.z;
    const int pidx = y * WW + x0;

    const float* pi = inp + b * CHW + pidx;
    const float* pt = tgt + b * CHW + pidx;

    // centers, 2 pixels x 3 channels x 2 tensors — aligned float2 loads
    const float2 ci0 = __ldg((const float2*)(pi));
    const float2 ci1 = __ldg((const float2*)(pi + HWSZ));
    const float2 ci2 = __ldg((const float2*)(pi + 2 * HWSZ));
    const float2 ct0 = __ldg((const float2*)(pt));
    const float2 ct1 = __ldg((const float2*)(pt + HWSZ));
    const float2 ct2 = __ldg((const float2*)(pt + 2 * HWSZ));

    const float iA0 = ci0.x, iA1 = ci1.x, iA2 = ci2.x;   // pixel0
    const float tA0 = ct0.x, tA1 = ct1.x, tA2 = ct2.x;
    const float iB0 = ci0.y, iB1 = ci1.y, iB2 = ci2.y;   // pixel1
    const float tB0 = ct0.y, tB1 = ct1.y, tB2 = ct2.y;

    float wky[4];
    wky[0] = 1.0f;
    wky[1] = __expf(-1.0f * INV2SS);
    wky[2] = __expf(-4.0f * INV2SS);
    wky[3] = __expf(-9.0f * INV2SS);

    float pacc = 0.0f;

#pragma unroll
    for (int dy = 0; dy <= 3; dy++) {
        const bool vy = (y + dy) < HH;          // dy==0: always true
        const int k0 = (dy == 0) ? 1 : -3;      // compile-time bounds
#pragma unroll
        for (int k = -3; k <= 4; k++) {
            if (k < k0) continue;               // compile-time skip
            const bool ok = vy && ((unsigned)(x0 + k) < (unsigned)WW);
            if (ok) {
                const int q = dy * WW + k;      // compile-time immediate
                const float iq0 = __ldg(pi + q);
                const float iq1 = __ldg(pi + q + HWSZ);
                const float iq2 = __ldg(pi + q + 2 * HWSZ);
                const float tq0 = __ldg(pt + q);
                const float tq1 = __ldg(pt + q + HWSZ);
                const float tq2 = __ldg(pt + q + 2 * HWSZ);

                // pixel0 term at dx = k  (half-set: dy>0 any k<=3; dy==0 k>=1)
                if (k <= 3) {
                    const int adx = k < 0 ? -k : k;
                    const float ws = wky[dy] * wky[adx];
                    const float sconst = (float)(dy * dy + k * k) * INV2SS;
                    pacc += pair_term(iA0, iA1, iA2, tA0, tA1, tA2,
                                      iq0, iq1, iq2, tq0, tq1, tq2,
                                      ws, sconst);
                }
                // pixel1 term at dx = k-1 (dy==0 requires dx>=1 -> k>=2)
                if (k - 1 >= ((dy == 0) ? 1 : -3)) {
                    const int dx1 = k - 1;
                    const int adx = dx1 < 0 ? -dx1 : dx1;
                    const float ws = wky[dy] * wky[adx];
                    const float sconst = (float)(dy * dy + dx1 * dx1) * INV2SS;
                    pacc += pair_term(iB0, iB1, iB2, tB0, tB1, tB2,
                                      iq0, iq1, iq2, tq0, tq1, tq2,
                                      ws, sconst);
                }
            }
        }
    }

    const float l2 = (iA0 - tA0) * (iA0 - tA0)
                   + (iA1 - tA1) * (iA1 - tA1)
                   + (iA2 - tA2) * (iA2 - tA2)
                   + (iB0 - tB0) * (iB0 - tB0)
                   + (iB1 - tB1) * (iB1 - tB1)
                   + (iB2 - tB2) * (iB2 - tB2);
    const float acc = fmaf(2.0f, pacc, l2);

    reduce_add(acc, out, threadIdx.y * 32 + threadIdx.x);
}

// Border kernel: only the clamped (out-of-bounds) ordered terms, weight 1.
__global__ __launch_bounds__(256)
void border_kernel(const float* __restrict__ inp,
                   const float* __restrict__ tgt,
                   float* __restrict__ out) {
    const int gid = blockIdx.x * 256 + threadIdx.x;
    float acc = 0.0f;

    if (gid < NBTOT) {
        const int b = gid / NBORDER;
        const int r = gid % NBORDER;
        int x, y;
        if (r < 3 * WW) {                    // top rows 0..2
            y = r / WW; x = r % WW;
        } else if (r < 6 * WW) {             // bottom rows 381..383
            const int r2 = r - 3 * WW;
            y = (HH - 3) + r2 / WW; x = r2 % WW;
        } else {                             // side cols, rows 3..380
            const int r3 = r - 6 * WW;
            y = 3 + r3 / 6;
            const int c = r3 % 6;
            x = (c < 3) ? c : (WW - 6 + c);  // 0,1,2 or 381,382,383
        }
        const int pidx = y * WW + x;
        const float* pi = inp + b * CHW + pidx;
        const float* pt = tgt + b * CHW + pidx;

        const float i0 = pi[0], i1 = pi[HWSZ], i2 = pi[2 * HWSZ];
        const float t0 = pt[0], t1 = pt[HWSZ], t2 = pt[2 * HWSZ];

        float wky[4];
        wky[0] = 1.0f;
        wky[1] = __expf(-1.0f * INV2SS);
        wky[2] = __expf(-4.0f * INV2SS);
        wky[3] = __expf(-9.0f * INV2SS);

#pragma unroll 1
        for (int dy = -3; dy <= 3; dy++) {
#pragma unroll 1
            for (int dx = -3; dx <= 3; dx++) {
                if (dy == 0 && dx == 0) continue;
                int qx = x + dx, qy = y + dy;
                const bool oob = ((unsigned)qx >= (unsigned)WW) ||
                                 ((unsigned)qy >= (unsigned)HH);
                if (oob) {
                    qx = qx < 0 ? 0 : (qx >= WW ? WW - 1 : qx);
                    qy = qy < 0 ? 0 : (qy >= HH ? HH - 1 : qy);
                    const int q = (qy - y) * WW + (qx - x);

                    const float iq0 = __ldg(pi + q);
                    const float iq1 = __ldg(pi + q + HWSZ);
                    const float iq2 = __ldg(pi + q + 2 * HWSZ);
                    const float tq0 = __ldg(pt + q);
                    const float tq1 = __ldg(pt + q + HWSZ);
                    const float tq2 = __ldg(pt + q + 2 * HWSZ);

                    const int ady = dy < 0 ? -dy : dy;
                    const int adx = dx < 0 ? -dx : dx;
                    const float ws = wky[ady] * wky[adx];
                    const float sconst = (float)(dy * dy + dx * dx) * INV2SS;

                    acc += pair_term(i0, i1, i2, t0, t1, t2,
                                     iq0, iq1, iq2, tq0, tq1, tq2,
                                     ws, sconst);
                }
            }
        }
    }

    reduce_add(acc, out, threadIdx.x);
}

extern "C" void kernel_launch(void* const* d_in, const int* in_sizes, int n_in,
                              void* d_out, int out_size) {
    (void)in_sizes; (void)n_in;
    const float* inp = (const float*)d_in[0];
    const float* tgt = (const float*)d_in[1];
    float* out = (float*)d_out;

    if (out_size >= 1) cudaMemsetAsync(out, 0, sizeof(float));

    border_kernel<<<(NBTOT + 255) / 256, 256>>>(inp, tgt, out);

    dim3 block(32, 8, 1);
    dim3 grid(WW / (32 * 2), HH / 8, BB);   // 2 pixels per thread in x
    pair_kernel<<<grid, block>>>(inp, tgt, out);
}

// round 10
// speedup vs baseline: 1.1630x; 1.1630x over previous
#include <cuda_runtime.h>
#include <math.h>

#define BB 4
#define CC 3
#define HH 384
#define WW 384
#define HWSZ (HH * WW)
#define CHW (CC * HWSZ)

#define INV2SC 50.0f            // 1/(2*0.1^2)
#define INV2SS (1.0f / 98.0f)   // 1/(2*7^2)
#define EPS_LP 1e-6f

// Border pixels per image: 2 strips of 3x384 + 378 rows x 6 cols
#define NBORDER (2 * 3 * WW + (HH - 6) * 6)   // 4572
#define NBTOT (NBORDER * BB)                  // 18288
#define NBBLK ((NBTOT + 255) / 256)           // 72

// lp(d) = (d*d + eps)^0.4
__device__ __forceinline__ float lp_term(float d) {
    return __powf(fmaf(d, d, EPS_LP), 0.4f);
}

// warp -> block reduction, one atomic per block (pre-scaled by 1/n).
// tid MUST be the linear 0..255 thread id within the block.
__device__ __forceinline__ void reduce_add(float acc, float* out, int tid) {
    const unsigned FULL = 0xFFFFFFFFu;
#pragma unroll
    for (int off = 16; off > 0; off >>= 1)
        acc += __shfl_down_sync(FULL, acc, off);
    __shared__ float wsum[8];
    const int wid = tid >> 5, lid = tid & 31;
    if (lid == 0) wsum[wid] = acc;
    __syncthreads();
    if (wid == 0) {
        float v = (lid < 8) ? wsum[lid] : 0.0f;
#pragma unroll
        for (int off = 4; off > 0; off >>= 1)
            v += __shfl_down_sync(FULL, v, off);
        if (lid == 0) {
            const float inv_n = 1.0f / (float)(BB * CC * HH * WW);
            atomicAdd(out, v * inv_n);
        }
    }
}

// Border path: only the clamped (out-of-bounds) ordered terms, weight 1.
// Runs in the z == BB grid slice. tid is the LINEAR thread id (R8's bug was
// using threadIdx.x here with a (32,8) block — 8x duplicated work + smem race).
__device__ __noinline__ void border_path(const float* __restrict__ inp,
                                         const float* __restrict__ tgt,
                                         float* __restrict__ out, int tid) {
    const int bid = blockIdx.y * gridDim.x + blockIdx.x;
    const int gid = bid * 256 + tid;
    float acc = 0.0f;

    if (gid < NBTOT) {
        const int b = gid / NBORDER;
        const int r = gid % NBORDER;
        int x, y;
        if (r < 3 * WW) {                    // top rows 0..2
            y = r / WW; x = r % WW;
        } else if (r < 6 * WW) {             // bottom rows 381..383
            const int r2 = r - 3 * WW;
            y = (HH - 3) + r2 / WW; x = r2 % WW;
        } else {                             // side cols, rows 3..380
            const int r3 = r - 6 * WW;
            y = 3 + r3 / 6;
            const int c = r3 % 6;
            x = (c < 3) ? c : (WW - 6 + c);  // 0,1,2 or 381,382,383
        }
        const int pidx = y * WW + x;
        const float* pi = inp + b * CHW + pidx;
        const float* pt = tgt + b * CHW + pidx;

        const float i0 = pi[0], i1 = pi[HWSZ], i2 = pi[2 * HWSZ];
        const float t0 = pt[0], t1 = pt[HWSZ], t2 = pt[2 * HWSZ];

        float wky[4];
        wky[0] = 1.0f;
        wky[1] = __expf(-1.0f * INV2SS);
        wky[2] = __expf(-4.0f * INV2SS);
        wky[3] = __expf(-9.0f * INV2SS);

#pragma unroll 1
        for (int dy = -3; dy <= 3; dy++) {
#pragma unroll 1
            for (int dx = -3; dx <= 3; dx++) {
                if (dy == 0 && dx == 0) continue;
                int qx = x + dx, qy = y + dy;
                const bool oob = ((unsigned)qx >= (unsigned)WW) ||
                                 ((unsigned)qy >= (unsigned)HH);
                if (oob) {
                    qx = qx < 0 ? 0 : (qx >= WW ? WW - 1 : qx);
                    qy = qy < 0 ? 0 : (qy >= HH ? HH - 1 : qy);
                    const int q = (qy - y) * WW + (qx - x);  // rel to pidx

                    const float iq0 = __ldg(pi + q);
                    const float iq1 = __ldg(pi + q + HWSZ);
                    const float iq2 = __ldg(pi + q + 2 * HWSZ);
                    const float tq0 = __ldg(pt + q);
                    const float tq1 = __ldg(pt + q + HWSZ);
                    const float tq2 = __ldg(pt + q + 2 * HWSZ);

                    const float d0 = i0 - iq0, d1 = i1 - iq1, d2 = i2 - iq2;
                    const float e0 = t0 - tq0, e1 = t1 - tq1, e2 = t2 - tq2;

                    const float cd = fmaf(e0, e0, fmaf(e1, e1, e2 * e2));
                    const int ady = dy < 0 ? -dy : dy;
                    const int adx = dx < 0 ? -dx : dx;
                    const float ws = wky[ady] * wky[adx];
                    const float sconst = (float)(dy * dy + dx * dx) * INV2SS;
                    const float wcs = __expf(-fmaf(cd, INV2SC, sconst));

                    const float sm = lp_term(d0) + lp_term(d1) + lp_term(d2);
                    const float ed = lp_term(fabsf(d0) - fabsf(e0))
                                   + lp_term(fabsf(d1) - fabsf(e1))
                                   + lp_term(fabsf(d2) - fabsf(e2));

                    acc = fmaf(wcs, sm, acc);
                    acc = fmaf(ws - wcs, ed, acc);
                }
            }
        }
    }

    reduce_add(acc, out, tid);
}

// One kernel. z < BB: clean hot path (byte-identical math to the 57.9us R7
// pair_kernel). z == BB: 72 border blocks, remaining blocks exit immediately.
__global__ __launch_bounds__(256)
void loss_kernel(const float* __restrict__ inp,
                 const float* __restrict__ tgt,
                 float* __restrict__ out) {
    const int tid = threadIdx.y * 32 + threadIdx.x;
    const int b = blockIdx.z;
    if (b >= BB) {                 // border slice (block-uniform branch)
        if (blockIdx.y * gridDim.x + blockIdx.x >= NBBLK) return;
        border_path(inp, tgt, out, tid);
        return;
    }

    const int x = blockIdx.x * 32 + threadIdx.x;
    const int y = blockIdx.y * 8 + threadIdx.y;
    const int pidx = y * WW + x;

    const float* pi = inp + b * CHW + pidx;
    const float* pt = tgt + b * CHW + pidx;

    const float i0 = pi[0], i1 = pi[HWSZ], i2 = pi[2 * HWSZ];
    const float t0 = pt[0], t1 = pt[HWSZ], t2 = pt[2 * HWSZ];

    float wky[4];
    wky[0] = 1.0f;
    wky[1] = __expf(-1.0f * INV2SS);
    wky[2] = __expf(-4.0f * INV2SS);
    wky[3] = __expf(-9.0f * INV2SS);

    float pacc = 0.0f;

#pragma unroll
    for (int dy = 0; dy <= 3; dy++) {
        const bool vy = (y + dy) < HH;
#pragma unroll
        for (int dx = -3; dx <= 3; dx++) {
            if (dy == 0 && dx <= 0) continue;      // compile-time
            const bool v = vy && ((unsigned)(x + dx) < (unsigned)WW);
            if (v) {
                const int q = dy * WW + dx;        // compile-time immediate
                const float iq0 = __ldg(pi + q);
                const float iq1 = __ldg(pi + q + HWSZ);
                const float iq2 = __ldg(pi + q + 2 * HWSZ);
                const float tq0 = __ldg(pt + q);
                const float tq1 = __ldg(pt + q + HWSZ);
                const float tq2 = __ldg(pt + q + 2 * HWSZ);

                const float d0 = i0 - iq0, d1 = i1 - iq1, d2 = i2 - iq2;
                const float e0 = t0 - tq0, e1 = t1 - tq1, e2 = t2 - tq2;

                const float cd = fmaf(e0, e0, fmaf(e1, e1, e2 * e2));
                const int adx = dx < 0 ? -dx : dx;
                const float ws = wky[dy] * wky[adx];
                const float sconst = (float)(dy * dy + dx * dx) * INV2SS;
                const float wcs = __expf(-fmaf(cd, INV2SC, sconst)); // ws*wc

                const float sm = lp_term(d0) + lp_term(d1) + lp_term(d2);
                const float ed = lp_term(fabsf(d0) - fabsf(e0))
                               + lp_term(fabsf(d1) - fabsf(e1))
                               + lp_term(fabsf(d2) - fabsf(e2));

                pacc = fmaf(wcs, sm, pacc);
                pacc = fmaf(ws - wcs, ed, pacc);
            }
        }
    }

    const float l2 = (i0 - t0) * (i0 - t0)
                   + (i1 - t1) * (i1 - t1)
                   + (i2 - t2) * (i2 - t2);
    const float acc = fmaf(2.0f, pacc, l2);

    reduce_add(acc, out, tid);
}

extern "C" void kernel_launch(void* const* d_in, const int* in_sizes, int n_in,
                              void* d_out, int out_size) {
    (void)in_sizes; (void)n_in;
    const float* inp = (const float*)d_in[0];
    const float* tgt = (const float*)d_in[1];
    float* out = (float*)d_out;

    if (out_size >= 1) cudaMemsetAsync(out, 0, sizeof(float));

    dim3 block(32, 8, 1);
    dim3 grid(WW / 32, HH / 8, BB + 1);   // z == BB: border slice
    loss_kernel<<<grid, block>>>(inp, tgt, out);
}

// round 11
// speedup vs baseline: 1.2437x; 1.0694x over previous
#include <cuda_runtime.h>
#include <math.h>

#define BB 4
#define CC 3
#define HH 384
#define WW 384
#define HWSZ (HH * WW)
#define CHW (CC * HWSZ)

#define INV2SC 50.0f            // 1/(2*0.1^2)
#define INV2SS (1.0f / 98.0f)   // 1/(2*7^2)
#define EPS_LP 1e-6f

// Border pixels per image: 2 strips of 3x384 + 378 rows x 6 cols
#define NBORDER (2 * 3 * WW + (HH - 6) * 6)   // 4572
#define NBTOT (NBORDER * BB)                  // 18288
#define NBBLK ((NBTOT + 255) / 256)           // 72

// lp(d) = (d*d + eps)^0.4
__device__ __forceinline__ float lp_term(float d) {
    return __powf(fmaf(d, d, EPS_LP), 0.4f);
}

// warp -> block reduction, one atomic per block (pre-scaled by 1/n).
// tid MUST be the linear 0..255 thread id within the block.
__device__ __forceinline__ void reduce_add(float acc, float* out, int tid) {
    const unsigned FULL = 0xFFFFFFFFu;
#pragma unroll
    for (int off = 16; off > 0; off >>= 1)
        acc += __shfl_down_sync(FULL, acc, off);
    __shared__ float wsum[8];
    const int wid = tid >> 5, lid = tid & 31;
    if (lid == 0) wsum[wid] = acc;
    __syncthreads();
    if (wid == 0) {
        float v = (lid < 8) ? wsum[lid] : 0.0f;
#pragma unroll
        for (int off = 4; off > 0; off >>= 1)
            v += __shfl_down_sync(FULL, v, off);
        if (lid == 0) {
            const float inv_n = 1.0f / (float)(BB * CC * HH * WW);
            atomicAdd(out, v * inv_n);
        }
    }
}

// Border path: only the clamped (out-of-bounds) ordered terms, weight 1.
// Runs in the z == 0 grid slice so these 72 blocks are scheduled FIRST and
// overlap with the first hot wave (at z == BB they ran in the tail: +10us).
__device__ __noinline__ void border_path(const float* __restrict__ inp,
                                         const float* __restrict__ tgt,
                                         float* __restrict__ out, int tid) {
    const int bid = blockIdx.y * gridDim.x + blockIdx.x;
    const int gid = bid * 256 + tid;
    float acc = 0.0f;

    if (gid < NBTOT) {
        const int b = gid / NBORDER;
        const int r = gid % NBORDER;
        int x, y;
        if (r < 3 * WW) {                    // top rows 0..2
            y = r / WW; x = r % WW;
        } else if (r < 6 * WW) {             // bottom rows 381..383
            const int r2 = r - 3 * WW;
            y = (HH - 3) + r2 / WW; x = r2 % WW;
        } else {                             // side cols, rows 3..380
            const int r3 = r - 6 * WW;
            y = 3 + r3 / 6;
            const int c = r3 % 6;
            x = (c < 3) ? c : (WW - 6 + c);  // 0,1,2 or 381,382,383
        }
        const int pidx = y * WW + x;
        const float* pi = inp + b * CHW + pidx;
        const float* pt = tgt + b * CHW + pidx;

        const float i0 = pi[0], i1 = pi[HWSZ], i2 = pi[2 * HWSZ];
        const float t0 = pt[0], t1 = pt[HWSZ], t2 = pt[2 * HWSZ];

        float wky[4];
        wky[0] = 1.0f;
        wky[1] = __expf(-1.0f * INV2SS);
        wky[2] = __expf(-4.0f * INV2SS);
        wky[3] = __expf(-9.0f * INV2SS);

#pragma unroll 1
        for (int dy = -3; dy <= 3; dy++) {
#pragma unroll 1
            for (int dx = -3; dx <= 3; dx++) {
                if (dy == 0 && dx == 0) continue;
                int qx = x + dx, qy = y + dy;
                const bool oob = ((unsigned)qx >= (unsigned)WW) ||
                                 ((unsigned)qy >= (unsigned)HH);
                if (oob) {
                    qx = qx < 0 ? 0 : (qx >= WW ? WW - 1 : qx);
                    qy = qy < 0 ? 0 : (qy >= HH ? HH - 1 : qy);
                    const int q = (qy - y) * WW + (qx - x);  // rel to pidx

                    const float iq0 = __ldg(pi + q);
                    const float iq1 = __ldg(pi + q + HWSZ);
                    const float iq2 = __ldg(pi + q + 2 * HWSZ);
                    const float tq0 = __ldg(pt + q);
                    const float tq1 = __ldg(pt + q + HWSZ);
                    const float tq2 = __ldg(pt + q + 2 * HWSZ);

                    const float d0 = i0 - iq0, d1 = i1 - iq1, d2 = i2 - iq2;
                    const float e0 = t0 - tq0, e1 = t1 - tq1, e2 = t2 - tq2;

                    const float cd = fmaf(e0, e0, fmaf(e1, e1, e2 * e2));
                    const int ady = dy < 0 ? -dy : dy;
                    const int adx = dx < 0 ? -dx : dx;
                    const float ws = wky[ady] * wky[adx];
                    const float sconst = (float)(dy * dy + dx * dx) * INV2SS;
                    const float wcs = __expf(-fmaf(cd, INV2SC, sconst));

                    const float sm = lp_term(d0) + lp_term(d1) + lp_term(d2);
                    const float ed = lp_term(fabsf(d0) - fabsf(e0))
                                   + lp_term(fabsf(d1) - fabsf(e1))
                                   + lp_term(fabsf(d2) - fabsf(e2));

                    acc = fmaf(wcs, sm, acc);
                    acc = fmaf(ws - wcs, ed, acc);
                }
            }
        }
    }

    reduce_add(acc, out, tid);
}

// One kernel. z == 0: border slice (72 active blocks, scheduled first,
// overlaps the hot waves). z >= 1: clean hot path for image b = z-1
// (byte-identical math to the 57.9us R7 pair_kernel).
__global__ __launch_bounds__(256)
void loss_kernel(const float* __restrict__ inp,
                 const float* __restrict__ tgt,
                 float* __restrict__ out) {
    const int tid = threadIdx.y * 32 + threadIdx.x;
    if (blockIdx.z == 0) {         // border slice (block-uniform branch)
        if (blockIdx.y * gridDim.x + blockIdx.x >= NBBLK) return;
        border_path(inp, tgt, out, tid);
        return;
    }
    const int b = blockIdx.z - 1;

    const int x = blockIdx.x * 32 + threadIdx.x;
    const int y = blockIdx.y * 8 + threadIdx.y;
    const int pidx = y * WW + x;

    const float* pi = inp + b * CHW + pidx;
    const float* pt = tgt + b * CHW + pidx;

    const float i0 = pi[0], i1 = pi[HWSZ], i2 = pi[2 * HWSZ];
    const float t0 = pt[0], t1 = pt[HWSZ], t2 = pt[2 * HWSZ];

    float wky[4];
    wky[0] = 1.0f;
    wky[1] = __expf(-1.0f * INV2SS);
    wky[2] = __expf(-4.0f * INV2SS);
    wky[3] = __expf(-9.0f * INV2SS);

    float pacc = 0.0f;

#pragma unroll
    for (int dy = 0; dy <= 3; dy++) {
        const bool vy = (y + dy) < HH;
#pragma unroll
        for (int dx = -3; dx <= 3; dx++) {
            if (dy == 0 && dx <= 0) continue;      // compile-time
            const bool v = vy && ((unsigned)(x + dx) < (unsigned)WW);
            if (v) {
                const int q = dy * WW + dx;        // compile-time immediate
                const float iq0 = __ldg(pi + q);
                const float iq1 = __ldg(pi + q + HWSZ);
                const float iq2 = __ldg(pi + q + 2 * HWSZ);
                const float tq0 = __ldg(pt + q);
                const float tq1 = __ldg(pt + q + HWSZ);
                const float tq2 = __ldg(pt + q + 2 * HWSZ);

                const float d0 = i0 - iq0, d1 = i1 - iq1, d2 = i2 - iq2;
                const float e0 = t0 - tq0, e1 = t1 - tq1, e2 = t2 - tq2;

                const float cd = fmaf(e0, e0, fmaf(e1, e1, e2 * e2));
                const int adx = dx < 0 ? -dx : dx;
                const float ws = wky[dy] * wky[adx];
                const float sconst = (float)(dy * dy + dx * dx) * INV2SS;
                const float wcs = __expf(-fmaf(cd, INV2SC, sconst)); // ws*wc

                const float sm = lp_term(d0) + lp_term(d1) + lp_term(d2);
                const float ed = lp_term(fabsf(d0) - fabsf(e0))
                               + lp_term(fabsf(d1) - fabsf(e1))
                               + lp_term(fabsf(d2) - fabsf(e2));

                pacc = fmaf(wcs, sm, pacc);
                pacc = fmaf(ws - wcs, ed, pacc);
            }
        }
    }

    const float l2 = (i0 - t0) * (i0 - t0)
                   + (i1 - t1) * (i1 - t1)
                   + (i2 - t2) * (i2 - t2);
    const float acc = fmaf(2.0f, pacc, l2);

    reduce_add(acc, out, tid);
}

extern "C" void kernel_launch(void* const* d_in, const int* in_sizes, int n_in,
                              void* d_out, int out_size) {
    (void)in_sizes; (void)n_in;
    const float* inp = (const float*)d_in[0];
    const float* tgt = (const float*)d_in[1];
    float* out = (float*)d_out;

    if (out_size >= 1) cudaMemsetAsync(out, 0, sizeof(float));

    dim3 block(32, 8, 1);
    dim3 grid(WW / 32, HH / 8, BB + 1);   // z == 0: border slice; z-1 = image
    loss_kernel<<<grid, block>>>(inp, tgt, out);
}